// round 12
// baseline (speedup 1.0000x reference)
#include <cuda_runtime.h>
#include <cstdint>

#define B_     16
#define P_     784
#define D_     10000
#define WPITCH 320
#define NROW_  1040        // 784 pw rows + 256 vw rows
#define NRB_   520         // k_pack blocks: 2 rows each
#define NXB_   25          // extra k_pack blocks for x quantize
#define NG_    40          // wordgroups of 8 words
#define NC_    16          // chunks of 49 positions

// ---- device scratch ----
__device__ unsigned g_pack[NROW_ * WPITCH];        // [row][word] row-major (1.33 MB)
__device__ unsigned char g_idxb[32 * 16 * 32];     // level bytes [c*2+ph][b][32B] (16 KB)
__device__ unsigned g_part[NC_ * 6 * 16 * WPITCH]; // 6-plane partials (1.97 MB)

__device__ __forceinline__ unsigned maj3(unsigned a, unsigned b, unsigned c) {
    return (a & b) | (a & c) | (b & c);   // single LOP3
}

// ============ K1: pack sign bits (row-major), quantize x ============
// Word W: bit l <-> column 128*(W>>2) + 4*l + (W&3)
__global__ __launch_bounds__(512, 2)
void k_pack(const float* __restrict__ x,
            const float* __restrict__ pw,
            const float* __restrict__ vw)
{
    int bid = blockIdx.x;
    if (bid < NRB_) {
        int wid = threadIdx.x >> 5, lane = threadIdx.x & 31;
        int row = bid * 2 + (wid >> 3);           // warps 0-7 row A, 8-15 row B
        int wq  = wid & 7;
        const float* src = (row < P_) ? (pw + (size_t)row * D_)
                                      : (vw + (size_t)(row - P_) * D_);
        float4 f[10];                              // MLP=10 per thread
        #pragma unroll
        for (int k = 0; k < 10; k++) {
            int g   = wq + k * 8;
            int col = g * 128 + lane * 4;
            bool ok = (g < 79) && (col + 3 < D_);
            f[k] = ok ? *reinterpret_cast<const float4*>(src + col)
                      : make_float4(1.f, 1.f, 1.f, 1.f);
        }
        #pragma unroll
        for (int k = 0; k < 10; k++) {
            int g = wq + k * 8;
            if (g < 79) {                          // warp-uniform
                unsigned m0 = __ballot_sync(0xffffffffu, f[k].x < 0.f);
                unsigned m1 = __ballot_sync(0xffffffffu, f[k].y < 0.f);
                unsigned m2 = __ballot_sync(0xffffffffu, f[k].z < 0.f);
                unsigned m3 = __ballot_sync(0xffffffffu, f[k].w < 0.f);
                if (lane < 4) {
                    unsigned mm = (lane == 0) ? m0 : (lane == 1) ? m1
                                 : (lane == 2) ? m2 : m3;
                    g_pack[row * WPITCH + g * 4 + lane] = mm;
                }
            }
        }
    } else {
        int i = (bid - NRB_) * 512 + threadIdx.x;
        if (i < B_ * P_) {
            int b = i / P_, p = i - b * P_;
            int c = p / 49, r = p - c * 49;
            int ph = (r >= 25) ? 1 : 0;
            int j  = r - ph * 25;
            int q = __float2int_rn(x[i] * 255.0f); // matches jnp.round (RN-even)
            q = max(0, min(255, q));
            g_idxb[((c * 2 + ph) * 16 + b) * 32 + j] = (unsigned char)q;
        }
    }
}

// ============ K2: accumulate 49 positions -> 6-plane partials ============
// Block = (g of 8 words, chunk c of 49 p). Thread = (b, ph, w).
__global__ __launch_bounds__(256, 4)
void k_acc()
{
    __shared__ unsigned vw_s[256 * 9];    // [lev][8 words pad 9]  9.2 KB
    __shared__ unsigned pw_s[49 * 8];     // [pos][word]           1.6 KB

    const int g  = blockIdx.x >> 4;
    const int c  = blockIdx.x & 15;
    const int t  = threadIdx.x;
    const int b  = t >> 4;
    const int ph = (t >> 3) & 1;          // lane bit 3 -> shfl_xor 8 pairs
    const int w  = t & 7;

    // ---- tile fills ----
    for (int i = t; i < 2048; i += 256)
        vw_s[(i >> 3) * 9 + (i & 7)] =
            g_pack[(size_t)(P_ + (i >> 3)) * WPITCH + g * 8 + (i & 7)];
    for (int i = t; i < 49 * 8; i += 256)
        pw_s[i] = g_pack[(size_t)(c * 49 + (i >> 3)) * WPITCH + g * 8 + (i & 7)];

    // ---- level bytes (c, ph, b) -> registers ----
    unsigned u[7];
    {
        const uint4* ib = reinterpret_cast<const uint4*>(
            g_idxb + ((c * 2 + ph) * 16 + b) * 32);
        uint4 a0 = ib[0], a1 = ib[1];
        u[0]=a0.x; u[1]=a0.y; u[2]=a0.z; u[3]=a0.w;
        u[4]=a1.x; u[5]=a1.y; u[6]=a1.z;
    }
    __syncthreads();

    // ---- 25 (ph=0) / 24 (ph=1) positions; pw LDS conflict-free ----
    const unsigned* pwr = pw_s + ph * 25 * 8 + w;
    unsigned cc0 = 0, cc1 = 0, cc2 = 0, cc3 = 0, cc4 = 0;

    #pragma unroll
    for (int gg = 0; gg < 3; gg++) {      // 3 CSA groups of 7 -> 21
        unsigned s[7];
        #pragma unroll
        for (int jj = 0; jj < 7; jj++) {
            int j = gg * 7 + jj;                      // compile-time constant
            unsigned lev = (u[j >> 2] >> ((j & 3) * 8)) & 255u;
            s[jj] = vw_s[lev * 9 + w] ^ pwr[j * 8];
        }
        unsigned t1s = s[0] ^ s[1] ^ s[2], t1c = maj3(s[0], s[1], s[2]);
        unsigned t2s = s[3] ^ s[4] ^ s[5], t2c = maj3(s[3], s[4], s[5]);
        unsigned q0  = t1s ^ t2s ^ s[6],   t3c = maj3(t1s, t2s, s[6]);
        unsigned q1  = t1c ^ t2c ^ t3c;
        unsigned q2  = maj3(t1c, t2c, t3c);
        unsigned cr = cc0 & q0;            cc0 ^= q0;
        unsigned n1 = maj3(cc1, q1, cr);   cc1 = cc1 ^ q1 ^ cr;  cr = n1;
        unsigned n2 = maj3(cc2, q2, cr);   cc2 = cc2 ^ q2 ^ cr;  cr = n2;
        unsigned n3 = cc3 & cr;            cc3 ^= cr;            cr = n3;
        cc4 ^= cr;
    }
    {   // remainder: 21,22,23 (CSA3) + 24 if ph==0
        unsigned l0 = (u[5] >>  8) & 255u;
        unsigned l1 = (u[5] >> 16) & 255u;
        unsigned l2 = (u[5] >> 24) & 255u;
        unsigned s0 = vw_s[l0 * 9 + w] ^ pwr[21 * 8];
        unsigned s1 = vw_s[l1 * 9 + w] ^ pwr[22 * 8];
        unsigned s2 = vw_s[l2 * 9 + w] ^ pwr[23 * 8];
        unsigned q0 = s0 ^ s1 ^ s2, q1 = maj3(s0, s1, s2);
        unsigned cr = cc0 & q0;            cc0 ^= q0;
        unsigned n1 = maj3(cc1, q1, cr);   cc1 = cc1 ^ q1 ^ cr;  cr = n1;
        unsigned n2 = cc2 & cr;            cc2 ^= cr;            cr = n2;
        unsigned n3 = cc3 & cr;            cc3 ^= cr;            cr = n3;
        cc4 ^= cr;
        if (ph == 0) {
            unsigned l3 = u[6] & 255u;
            unsigned s3 = vw_s[l3 * 9 + w] ^ pwr[24 * 8];
            cr = cc0 & s3;  cc0 ^= s3;
            unsigned m1 = cc1 & cr;  cc1 ^= cr;  cr = m1;
            unsigned m2 = cc2 & cr;  cc2 ^= cr;  cr = m2;
            unsigned m3 = cc3 & cr;  cc3 ^= cr;  cr = m3;
            cc4 ^= cr;                            // max 25 < 32
        }
    }

    // ---- merge ph halves via shfl_xor 8: 5+5 -> 6 planes (max 49) ----
    {
        unsigned d0 = __shfl_xor_sync(0xffffffffu, cc0, 8);
        unsigned d1 = __shfl_xor_sync(0xffffffffu, cc1, 8);
        unsigned d2 = __shfl_xor_sync(0xffffffffu, cc2, 8);
        unsigned d3 = __shfl_xor_sync(0xffffffffu, cc3, 8);
        unsigned d4 = __shfl_xor_sync(0xffffffffu, cc4, 8);
        unsigned cr, n;
        cr = cc0 & d0;            cc0 ^= d0;
        n = maj3(cc1, d1, cr);    cc1 = cc1 ^ d1 ^ cr;  cr = n;
        n = maj3(cc2, d2, cr);    cc2 = cc2 ^ d2 ^ cr;  cr = n;
        n = maj3(cc3, d3, cr);    cc3 = cc3 ^ d3 ^ cr;  cr = n;
        n = maj3(cc4, d4, cr);    cc4 = cc4 ^ d4 ^ cr;  cr = n;
        if (ph == 0) {
            unsigned base = ((unsigned)(c * 6) * 16 + b) * WPITCH + g * 8 + w;
            g_part[base]               = cc0;
            g_part[base + 16u*WPITCH]  = cc1;
            g_part[base + 32u*WPITCH]  = cc2;
            g_part[base + 48u*WPITCH]  = cc3;
            g_part[base + 64u*WPITCH]  = cc4;
            g_part[base + 80u*WPITCH]  = cr;
        }
    }
}

// ============ K3: combine 16 chunks -> sign, store ============
// Block = g. Thread = (b, ch, w); ch splits chunks 0-7 / 8-15, shfl merge.
__global__ __launch_bounds__(256)
void k_fin(float* __restrict__ out)
{
    __shared__ unsigned br_s[16 * 8];     // [b][w]

    const int g  = blockIdx.x;
    const int t  = threadIdx.x;
    const int b  = t >> 4;
    const int ch = (t >> 3) & 1;
    const int w  = t & 7;

    unsigned P0=0,P1=0,P2=0,P3=0,P4=0,P5=0,P6=0,P7=0,P8=0;
    #pragma unroll
    for (int c8 = 0; c8 < 8; c8++) {
        int c = ch * 8 + c8;
        unsigned base = ((unsigned)(c * 6) * 16 + b) * WPITCH + g * 8 + w;
        unsigned a0 = g_part[base];
        unsigned a1 = g_part[base + 16u*WPITCH];
        unsigned a2 = g_part[base + 32u*WPITCH];
        unsigned a3 = g_part[base + 48u*WPITCH];
        unsigned a4 = g_part[base + 64u*WPITCH];
        unsigned a5 = g_part[base + 80u*WPITCH];
        unsigned cr, n;
        cr = P0 & a0;           P0 ^= a0;
        n = maj3(P1, a1, cr);   P1 = P1 ^ a1 ^ cr;  cr = n;
        n = maj3(P2, a2, cr);   P2 = P2 ^ a2 ^ cr;  cr = n;
        n = maj3(P3, a3, cr);   P3 = P3 ^ a3 ^ cr;  cr = n;
        n = maj3(P4, a4, cr);   P4 = P4 ^ a4 ^ cr;  cr = n;
        n = maj3(P5, a5, cr);   P5 = P5 ^ a5 ^ cr;  cr = n;
        n = P6 & cr;  P6 ^= cr;  cr = n;
        n = P7 & cr;  P7 ^= cr;  cr = n;
        P8 ^= cr;                              // max 392 < 512
    }
    // merge ch halves: 9+9 -> 10 planes (max 784)
    unsigned P9;
    {
        unsigned d0 = __shfl_xor_sync(0xffffffffu, P0, 8);
        unsigned d1 = __shfl_xor_sync(0xffffffffu, P1, 8);
        unsigned d2 = __shfl_xor_sync(0xffffffffu, P2, 8);
        unsigned d3 = __shfl_xor_sync(0xffffffffu, P3, 8);
        unsigned d4 = __shfl_xor_sync(0xffffffffu, P4, 8);
        unsigned d5 = __shfl_xor_sync(0xffffffffu, P5, 8);
        unsigned d6 = __shfl_xor_sync(0xffffffffu, P6, 8);
        unsigned d7 = __shfl_xor_sync(0xffffffffu, P7, 8);
        unsigned d8 = __shfl_xor_sync(0xffffffffu, P8, 8);
        unsigned cr, n;
        cr = P0 & d0;           P0 ^= d0;
        n = maj3(P1, d1, cr);   P1 = P1 ^ d1 ^ cr;  cr = n;
        n = maj3(P2, d2, cr);   P2 = P2 ^ d2 ^ cr;  cr = n;
        n = maj3(P3, d3, cr);   P3 = P3 ^ d3 ^ cr;  cr = n;
        n = maj3(P4, d4, cr);   P4 = P4 ^ d4 ^ cr;  cr = n;
        n = maj3(P5, d5, cr);   P5 = P5 ^ d5 ^ cr;  cr = n;
        n = maj3(P6, d6, cr);   P6 = P6 ^ d6 ^ cr;  cr = n;
        n = maj3(P7, d7, cr);   P7 = P7 ^ d7 ^ cr;  cr = n;
        n = maj3(P8, d8, cr);   P8 = P8 ^ d8 ^ cr;  cr = n;
        P9 = cr;
    }
    // borrow of (cnt - 392); 392 = bits 3,7,8.  br=1 <=> cnt<392 <=> +1
    if (ch == 0) {
        unsigned br = 0;
        br = ~P0 & br;  br = ~P1 & br;  br = ~P2 & br;
        br = ~P3 | br;
        br = ~P4 & br;  br = ~P5 & br;  br = ~P6 & br;
        br = ~P7 | br;  br = ~P8 | br;
        br = ~P9 & br;
        br_s[b * 8 + w] = br;
    }
    __syncthreads();

    // ---- coalesced sign store: group g covers cols [256g, 256g+256) ----
    {
        int c64 = t & 63;                 // column quad within group
        int sub = c64 >> 5;               // which 128-col sub-block
        unsigned l = (unsigned)(c64 & 31);
        int col = g * 256 + c64 * 4;
        #pragma unroll
        for (int bb = 0; bb < 4; bb++) {
            int bo = (t >> 6) * 4 + bb;
            if (col + 3 < D_) {
                const unsigned* brq = &br_s[bo * 8 + sub * 4];
                float4 v;
                v.x = __uint_as_float(0x3F800000u | ((((brq[0] >> l) & 1u) ^ 1u) << 31));
                v.y = __uint_as_float(0x3F800000u | ((((brq[1] >> l) & 1u) ^ 1u) << 31));
                v.z = __uint_as_float(0x3F800000u | ((((brq[2] >> l) & 1u) ^ 1u) << 31));
                v.w = __uint_as_float(0x3F800000u | ((((brq[3] >> l) & 1u) ^ 1u) << 31));
                *reinterpret_cast<float4*>(out + (size_t)bo * D_ + col) = v;
            }
        }
    }
}

extern "C" void kernel_launch(void* const* d_in, const int* in_sizes, int n_in,
                              void* d_out, int out_size)
{
    (void)in_sizes; (void)n_in; (void)out_size;
    const float* x  = (const float*)d_in[0];   // (16, 28, 28)
    const float* pw = (const float*)d_in[1];   // (784, 10000)
    const float* vw = (const float*)d_in[2];   // (256, 10000)
    float* out = (float*)d_out;                // (16, 10000)

    k_pack<<<NRB_ + NXB_, 512>>>(x, pw, vw);
    k_acc<<<NG_ * NC_, 256>>>();
    k_fin<<<NG_, 256>>>(out);
}

// round 13
// speedup vs baseline: 1.3643x; 1.3643x over previous
#include <cuda_runtime.h>
#include <cstdint>

#define B_    16
#define P_    784
#define D_    10000
#define NW_   316          // packed words per row: 79 groups x 4 (permuted ballot layout)
#define NROW_ 1040         // 784 pw rows + 256 vw rows
#define NXB_  25           // extra blocks for x quantize (512 thr each)

// ---- device scratch ----
__device__ unsigned g_packT[NW_ * NROW_];   // TRANSPOSED: [word][row]  (1.31 MB)
__device__ unsigned g_idxr[32 * 16 * 8];    // level bytes [ch][b][32B pitch] (16 KB)

__device__ __forceinline__ unsigned maj3(unsigned a, unsigned b, unsigned c) {
    return (a & b) | (a & c) | (b & c);   // single LOP3
}

// ============ K1: pack sign bits (transposed), quantize x ============
// Word W: bit l <-> column 128*(W>>2) + 4*l + (W&3)
__global__ __launch_bounds__(512)
void k_pack(const float* __restrict__ x,
            const float* __restrict__ pw,
            const float* __restrict__ vw)
{
    int bid = blockIdx.x;
    if (bid < NROW_) {
        const float* src = (bid < P_) ? (pw + (size_t)bid * D_)
                                      : (vw + (size_t)(bid - P_) * D_);
        int wid = threadIdx.x >> 5, lane = threadIdx.x & 31;

        float4 f[5];                        // MLP=5 per thread
        #pragma unroll
        for (int k = 0; k < 5; k++) {
            int g   = wid + k * 16;
            int col = g * 128 + lane * 4;
            bool ok = (g < 79) && (col + 3 < D_);
            f[k] = ok ? *reinterpret_cast<const float4*>(src + col)
                      : make_float4(1.f, 1.f, 1.f, 1.f);
        }
        #pragma unroll
        for (int k = 0; k < 5; k++) {
            int g = wid + k * 16;
            if (g < 79) {                   // warp-uniform
                unsigned m0 = __ballot_sync(0xffffffffu, f[k].x < 0.f);
                unsigned m1 = __ballot_sync(0xffffffffu, f[k].y < 0.f);
                unsigned m2 = __ballot_sync(0xffffffffu, f[k].z < 0.f);
                unsigned m3 = __ballot_sync(0xffffffffu, f[k].w < 0.f);
                if (lane < 4) {
                    unsigned mm = (lane == 0) ? m0 : (lane == 1) ? m1
                                 : (lane == 2) ? m2 : m3;
                    g_packT[(size_t)(g * 4 + lane) * NROW_ + bid] = mm;
                }
            }
        }
    } else {
        int i = (bid - NROW_) * 512 + threadIdx.x;
        if (i < B_ * P_) {
            int b = i / P_, p = i - b * P_;
            int ch, j;
            if (p < 400) { ch = p / 25;              j = p - ch * 25; }
            else         { ch = 16 + (p - 400) / 24; j = (p - 400) - (ch - 16) * 24; }
            int q = __float2int_rn(x[i] * 255.0f);   // matches jnp.round (RN-even)
            q = max(0, min(255, q));
            reinterpret_cast<unsigned char*>(g_idxr)[((ch * 16 + b) << 5) + j] =
                (unsigned char)q;
        }
    }
}

// ============ K2 (fused): accumulate + combine + compare + store ============
// One block per word (316 blocks x 512 threads). 32 p-chunks (16x25 + 16x24).
// launch_bounds(512, 2): ~61 regs so the 7 LDS pairs per CSA group batch (MLP).
__global__ __launch_bounds__(512, 2)
void k_acc(float* __restrict__ out)
{
    __shared__ unsigned pv_s[NROW_];        // pw bits [0..783], vw bits [784..1039]
    __shared__ unsigned part2[16][16][7];   // [warp][b][6 planes] pad 7 (7.2 KB)
    __shared__ unsigned br_s[16];

    const int w   = blockIdx.x;
    const int t   = threadIdx.x;
    const int wid = t >> 5, lane = t & 31;

    const unsigned* colbase = g_packT + (size_t)w * NROW_;
    for (int i = t; i < NROW_; i += 512) pv_s[i] = colbase[i];

    // thread = (b, chunk): chunk = wid*2 + (lane>>4); warps 0-7 len 25, 8-15 len 24
    const int b   = lane & 15;
    const int ph  = lane >> 4;
    const int ch  = wid * 2 + ph;
    const int start = (wid < 8) ? ch * 25 : 400 + (ch - 16) * 24;

    unsigned u[8];
    {
        const uint4* src = reinterpret_cast<const uint4*>(g_idxr + (ch * 16 + b) * 8);
        uint4 a0 = src[0], a1 = src[1];
        u[0]=a0.x; u[1]=a0.y; u[2]=a0.z; u[3]=a0.w;
        u[4]=a1.x; u[5]=a1.y; u[6]=a1.z; u[7]=a1.w;
    }
    __syncthreads();

    const unsigned* vw_s = pv_s + P_;
    const unsigned* ppwr = pv_s + start;
    unsigned cc0 = 0, cc1 = 0, cc2 = 0, cc3 = 0, cc4 = 0;

    // 3 groups of 7
    #pragma unroll
    for (int g = 0; g < 3; g++) {
        unsigned s[7];
        #pragma unroll
        for (int jj = 0; jj < 7; jj++) {
            int j = g * 7 + jj;                       // compile-time constant
            unsigned lev = (u[j >> 2] >> ((j & 3) * 8)) & 255u;
            s[jj] = vw_s[lev] ^ ppwr[j];
        }
        unsigned t1s = s[0] ^ s[1] ^ s[2], t1c = maj3(s[0], s[1], s[2]);
        unsigned t2s = s[3] ^ s[4] ^ s[5], t2c = maj3(s[3], s[4], s[5]);
        unsigned q0  = t1s ^ t2s ^ s[6],   t3c = maj3(t1s, t2s, s[6]);
        unsigned q1  = t1c ^ t2c ^ t3c;
        unsigned q2  = maj3(t1c, t2c, t3c);
        unsigned c = cc0 & q0;            cc0 ^= q0;
        unsigned n1 = maj3(cc1, q1, c);   cc1 = cc1 ^ q1 ^ c;  c = n1;
        unsigned n2 = maj3(cc2, q2, c);   cc2 = cc2 ^ q2 ^ c;  c = n2;
        unsigned n3 = cc3 & c;            cc3 ^= c;            c = n3;
        cc4 ^= c;
    }
    // remainder: positions 21,22,23 (CSA3) + 24 if len==25
    {
        unsigned l0 = (u[5] >>  8) & 255u;            // j=21
        unsigned l1 = (u[5] >> 16) & 255u;            // j=22
        unsigned l2 = (u[5] >> 24) & 255u;            // j=23
        unsigned s0 = vw_s[l0] ^ ppwr[21];
        unsigned s1 = vw_s[l1] ^ ppwr[22];
        unsigned s2 = vw_s[l2] ^ ppwr[23];
        unsigned q0 = s0 ^ s1 ^ s2, q1 = maj3(s0, s1, s2);
        unsigned c = cc0 & q0;            cc0 ^= q0;
        unsigned n1 = maj3(cc1, q1, c);   cc1 = cc1 ^ q1 ^ c;  c = n1;
        unsigned n2 = cc2 & c;            cc2 ^= c;            c = n2;
        unsigned n3 = cc3 & c;            cc3 ^= c;            c = n3;
        cc4 ^= c;
        if (wid < 8) {                                // warp-uniform
            unsigned l3 = u[6] & 255u;                // j=24
            unsigned s3 = vw_s[l3] ^ ppwr[24];
            unsigned cr = cc0 & s3;  cc0 ^= s3;
            unsigned m1 = cc1 & cr;  cc1 ^= cr;  cr = m1;
            unsigned m2 = cc2 & cr;  cc2 ^= cr;  cr = m2;
            unsigned m3 = cc3 & cr;  cc3 ^= cr;  cr = m3;
            cc4 ^= cr;                                // max 25 < 32
        }
    }

    // combine chunk pair (lane ^ 16): 5+5 planes -> 6 planes (max 49)
    {
        unsigned d0 = __shfl_xor_sync(0xffffffffu, cc0, 16);
        unsigned d1 = __shfl_xor_sync(0xffffffffu, cc1, 16);
        unsigned d2 = __shfl_xor_sync(0xffffffffu, cc2, 16);
        unsigned d3 = __shfl_xor_sync(0xffffffffu, cc3, 16);
        unsigned d4 = __shfl_xor_sync(0xffffffffu, cc4, 16);
        unsigned c, n;
        c = cc0 & d0;            cc0 ^= d0;
        n = maj3(cc1, d1, c);    cc1 = cc1 ^ d1 ^ c;  c = n;
        n = maj3(cc2, d2, c);    cc2 = cc2 ^ d2 ^ c;  c = n;
        n = maj3(cc3, d3, c);    cc3 = cc3 ^ d3 ^ c;  c = n;
        n = maj3(cc4, d4, c);    cc4 = cc4 ^ d4 ^ c;  c = n;
        if (lane < 16) {
            unsigned* pr = part2[wid][b];
            pr[0]=cc0; pr[1]=cc1; pr[2]=cc2; pr[3]=cc3; pr[4]=cc4; pr[5]=c;
        }
    }
    __syncthreads();

    // threads 0..15: combine 16 warps' 6-plane partials -> 10 planes, compare vs 392
    if (t < 16) {
        unsigned P0=0,P1=0,P2=0,P3=0,P4=0,P5=0,P6=0,P7=0,P8=0,P9=0;
        #pragma unroll
        for (int k = 0; k < 16; k++) {
            const unsigned* a = part2[k][t];
            unsigned c, n;
            c = P0 & a[0];           P0 ^= a[0];
            n = maj3(P1, a[1], c);   P1 = P1 ^ a[1] ^ c;  c = n;
            n = maj3(P2, a[2], c);   P2 = P2 ^ a[2] ^ c;  c = n;
            n = maj3(P3, a[3], c);   P3 = P3 ^ a[3] ^ c;  c = n;
            n = maj3(P4, a[4], c);   P4 = P4 ^ a[4] ^ c;  c = n;
            n = maj3(P5, a[5], c);   P5 = P5 ^ a[5] ^ c;  c = n;
            n = P6 & c;  P6 ^= c;  c = n;
            n = P7 & c;  P7 ^= c;  c = n;
            n = P8 & c;  P8 ^= c;  c = n;
            P9 ^= c;                                       // max 784 < 1024
        }
        // borrow of (cnt - 392); 392 = bits 3,7,8.  br=1 <=> cnt<392 <=> +1
        unsigned br = 0;
        br = ~P0 & br;  br = ~P1 & br;  br = ~P2 & br;
        br = ~P3 | br;
        br = ~P4 & br;  br = ~P5 & br;  br = ~P6 & br;
        br = ~P7 | br;  br = ~P8 | br;
        br = ~P9 & br;
        br_s[t] = br;
    }
    __syncthreads();

    // store: 512 signs (16 b x 32 bits), 1 per thread
    {
        int bb = t >> 5;
        int j  = t & 31;
        unsigned br = br_s[bb];
        int col = 128 * (w >> 2) + (w & 3) + 4 * j;
        if (col < D_) {
            unsigned sgn = ((br >> j) & 1u) ^ 1u;
            out[(size_t)bb * D_ + col] = __uint_as_float(0x3F800000u | (sgn << 31));
        }
    }
}

extern "C" void kernel_launch(void* const* d_in, const int* in_sizes, int n_in,
                              void* d_out, int out_size)
{
    (void)in_sizes; (void)n_in; (void)out_size;
    const float* x  = (const float*)d_in[0];   // (16, 28, 28)
    const float* pw = (const float*)d_in[1];   // (784, 10000)
    const float* vw = (const float*)d_in[2];   // (256, 10000)
    float* out = (float*)d_out;                // (16, 10000)

    k_pack<<<NROW_ + NXB_, 512>>>(x, pw, vw);
    k_acc<<<NW_, 512>>>(out);
}